// round 15
// baseline (speedup 1.0000x reference)
#include <cuda_runtime.h>
#include <cuda_bf16.h>

typedef unsigned int       u32;
typedef unsigned long long u64;

#define BATCH    4096
#define ATOMS    64
#define NATOMS   (BATCH * ATOMS)
#define FDIM     124
#define XROW     125
#define NTYPE    8
#define H1       64
#define H2       16
#define NA       64                  // atoms per chunk (16 per warp-pair)
#define NTHREADS 256
#define LISTCAP  40960
#define NSLOT    55                  // 55*8 = 440 CTAs ~= 148 SMs x 3

#define AP       68                  // u64 per A row
#define BPITCH   68                  // u64 per B row
#define W2PITCH  36                  // u64 per W2 row

// ---------------- SMEM layout (byte offsets) ---------------------------------
#define OFF_BP    0                          // Bp  u64[64][68] = 34816
#define OFF_W2P   34816                      // W2p u64[16][36] = 4608
#define OFF_A     39424                      // A   u64[64][68] = 34816
#define OFF_B1    74240                      // 256
#define OFF_B2    74496                      // 64
#define OFF_W3    74560                      // 64
#define OFF_PT    74624                      // s_pt f32[64][2] = 512
#define OFF_MISC  75136                      // 16
#define SMEM_TOTAL 75152                     // -> 3 CTAs/SM

// ---------------- device globals ---------------------------------------------
__device__ float d_c[NTYPE];               // c_t = MLP_t(0)
__device__ int   d_cnt[NTYPE];
__device__ int   d_list[NTYPE][LISTCAP];
__device__ u64   d_w1p[NTYPE][H1 * 64];    // [t][n][kpair] (lo<<32)|hi
__device__ u64   d_w2p[NTYPE][H2 * 32];    // [t][j][hpair]

// ---------------- helpers ----------------------------------------------------
__device__ __forceinline__ u32 cvt2bf(float hi_elem, float lo_elem) {
    u32 r;
    asm("cvt.rn.bf16x2.f32 %0, %1, %2;" : "=r"(r) : "f"(hi_elem), "f"(lo_elem));
    return r;
}
__device__ __forceinline__ u64 split_pack(float fx, float fy) {
    u32 hi = cvt2bf(fy, fx);
    float ha = __uint_as_float(hi << 16);
    float hb = __uint_as_float(hi & 0xFFFF0000u);
    u32 lo = cvt2bf(fy - hb, fx - ha);
    return ((u64)lo << 32) | hi;
}
__device__ __forceinline__ void mma16(float* d, u32 a0, u32 a1, u32 a2, u32 a3,
                                      u32 b0, u32 b1) {
    asm volatile(
        "mma.sync.aligned.m16n8k16.row.col.f32.bf16.bf16.f32 "
        "{%0,%1,%2,%3}, {%4,%5,%6,%7}, {%8,%9}, {%0,%1,%2,%3};"
        : "+f"(d[0]), "+f"(d[1]), "+f"(d[2]), "+f"(d[3])
        : "r"(a0), "r"(a1), "r"(a2), "r"(a3), "r"(b0), "r"(b1));
}
__device__ __forceinline__ u32 lo32(u64 v) { return (u32)v; }
__device__ __forceinline__ u32 hi32(u64 v) { return (u32)(v >> 32); }
#define BARP(id) asm volatile("bar.sync %0, 64;" :: "r"(id) : "memory")

// ---------------- kernel 0: fused setup (classify + weight prep) -------------
#define CLS_ATOMS 1024
#define CLS_BLOCKS (NATOMS / CLS_ATOMS)     // 256
__global__ __launch_bounds__(256)
void setup_kernel(const float* __restrict__ x,
                  const float* __restrict__ mask,
                  const float* __restrict__ W1,
                  const float* __restrict__ b1,
                  const float* __restrict__ W2,
                  const float* __restrict__ b2,
                  const float* __restrict__ W3,
                  const float* __restrict__ b3,
                  float* __restrict__ out) {
    const int tid = threadIdx.x;
    if (blockIdx.x < CLS_BLOCKS) {
        __shared__ int s_cnt[NTYPE];
        __shared__ int s_base[NTYPE];
        if (tid < NTYPE) s_cnt[tid] = 0;
        __syncthreads();
        const int a0 = blockIdx.x * CLS_ATOMS + tid * 4;
        int ty[4], rk[4];
        float mv[4];
        #pragma unroll
        for (int i = 0; i < 4; i++) {
            mv[i] = mask[a0 + i];
            ty[i] = (int)x[(size_t)(a0 + i) * XROW];
        }
        #pragma unroll
        for (int i = 0; i < 4; i++)
            rk[i] = (mv[i] != 0.f) ? atomicAdd(&s_cnt[ty[i]], 1) : -1;
        __syncthreads();
        if (tid < NTYPE) s_base[tid] = atomicAdd(&d_cnt[tid], s_cnt[tid]);
        __syncthreads();
        #pragma unroll
        for (int i = 0; i < 4; i++)
            if (rk[i] >= 0)
                d_list[ty[i]][s_base[ty[i]] + rk[i]] = a0 + i;
    } else {
        const int t = blockIdx.x - CLS_BLOCKS;
        for (int i = tid; i < H1 * 64; i += 256) {
            int n = i >> 6, p = i & 63;
            u64 w = 0;
            if (p < FDIM / 2) {
                float va = W1[(size_t)t * FDIM * H1 + (2 * p) * H1 + n];
                float vb = W1[(size_t)t * FDIM * H1 + (2 * p + 1) * H1 + n];
                w = split_pack(va, vb);
            }
            d_w1p[t][i] = w;
        }
        for (int i = tid; i < H2 * 32; i += 256) {
            int j = i >> 5, p = i & 31;
            float va = W2[(size_t)t * H1 * H2 + (2 * p) * H2 + j];
            float vb = W2[(size_t)t * H1 * H2 + (2 * p + 1) * H2 + j];
            d_w2p[t][i] = split_pack(va, vb);
        }
        for (int i = tid; i < BATCH / NTYPE; i += 256)
            out[t * (BATCH / NTYPE) + i] = 0.f;
        if (tid < 16) {
            const int g = tid;
            float v = b2[t * H2 + g];
            for (int h = 0; h < H1; h++)
                v += fmaxf(b1[t * H1 + h], 0.f) * W2[t * H1 * H2 + h * H2 + g];
            float o = fmaxf(v, 0.f) * W3[t * H2 + g];
            #pragma unroll
            for (int off = 8; off > 0; off >>= 1)
                o += __shfl_xor_sync(0xffffu, o, off);
            if (g == 0) d_c[t] = o + b3[t];
        }
    }
}

// ---------------- kernel 1: warp-pair MLP, register-pipelined gather ---------
__global__ __launch_bounds__(NTHREADS, 3)
void mol_kernel(const float* __restrict__ x,
                const float* __restrict__ b1,
                const float* __restrict__ b2,
                const float* __restrict__ W3,
                const float* __restrict__ b3,
                float* __restrict__ out) {
    extern __shared__ char smraw[];
    const int tid = threadIdx.x, wid = tid >> 5, lane = tid & 31;
    const int t = blockIdx.y;
    const int cnt = d_cnt[t];

    u64*   Bp   = (u64*)(smraw + OFF_BP);
    u64*   W2p  = (u64*)(smraw + OFF_W2P);
    u64*   Ap   = (u64*)(smraw + OFF_A);
    float* b1s  = (float*)(smraw + OFF_B1);
    float* b2s  = (float*)(smraw + OFF_B2);
    float* w3s  = (float*)(smraw + OFF_W3);
    float* s_pt = (float*)(smraw + OFF_PT);
    float* s_ms = (float*)(smraw + OFF_MISC);

    // ---- stage read-only shared data ONCE ----
    {
        const u64* w1 = d_w1p[t];
        for (int i = tid; i < H1 * 64; i += NTHREADS) {
            int n = i >> 6, p = i & 63;
            Bp[n * BPITCH + p] = w1[i];
        }
        const u64* w2 = d_w2p[t];
        for (int i = tid; i < H2 * 32; i += NTHREADS) {
            int j = i >> 5, p = i & 31;
            W2p[j * W2PITCH + p] = w2[i];
        }
        if (tid < H1) b1s[tid] = b1[t * H1 + tid];
        if (tid < H2) { b2s[tid] = b2[t * H2 + tid]; w3s[tid] = W3[t * H2 + tid]; }
        if (tid == 0) {
            float tot = 0.f;
            #pragma unroll
            for (int u = 0; u < NTYPE; u++) tot += d_c[u];
            s_ms[0] = b3[t] + (tot - d_c[t]);   // b3 + correction
        }
        if (tid < 128) {                        // zero k-pads once (never rewritten)
            int r = tid >> 1, kp = 62 + (tid & 1);
            Ap[r * AP + kp] = 0ull;
        }
    }
    __syncthreads();   // the ONLY block barrier

    const int pair = wid >> 1;               // 0..3
    const int wp   = wid & 1;                // warp-in-pair
    const int bid5 = pair + 1;               // named barrier id 1..4
    const int rr4  = lane >> 2;
    const int ka   = lane & 3;
    u64* Aw = Ap + pair * 16 * AP;           // pair's 16-row slab
    const float cst = s_ms[0];
    const int step = NSLOT * NA;

    // ---- register pipeline state: 8 rows x 4 floats ----
    float pf[8][4];
    int aid = 0;

    // prologue: ids + rows of first chunk
    {
        const int slot0 = blockIdx.x * NA + pair * 16;
        if (slot0 < cnt) {
            if (lane < 16)
                aid = d_list[t][min(slot0 + lane, cnt - 1)];
            #pragma unroll
            for (int rr = 0; rr < 8; rr++) {
                const int a = __shfl_sync(0xffffffffu, aid, wp * 8 + rr);
                const float* r = x + (size_t)a * XROW + 1;
                if (lane < 31) {
                    const int l2 = 2 * lane;
                    pf[rr][0] = r[l2];      pf[rr][1] = r[l2 + 1];
                    pf[rr][2] = r[l2 + 62]; pf[rr][3] = r[l2 + 63];
                }
            }
        }
    }

    // ---- persistent warp-pair chunk loop ----
    for (int base = blockIdx.x * NA; base < cnt; base += step) {
        const int slot0 = base + pair * 16;

        // ---- store phase: split prefetched rows into smem ----
        if (lane < 31) {
            #pragma unroll
            for (int rr = 0; rr < 8; rr++) {
                const int srow = wp * 8 + rr;
                Aw[srow * AP + lane]      = split_pack(pf[rr][0], pf[rr][1]);
                Aw[srow * AP + lane + 31] = split_pack(pf[rr][2], pf[rr][3]);
            }
        }
        BARP(bid5);   // pair's 16 rows complete

        // ---- pipeline: issue NEXT chunk's LDGs (consumed next iteration) ----
        int naid = 0;
        {
            const int nslot0 = slot0 + step;
            if (nslot0 - pair * 16 < cnt) {     // next base in range
                if (lane < 16)
                    naid = d_list[t][min(nslot0 + lane, cnt - 1)];
                #pragma unroll
                for (int rr = 0; rr < 8; rr++) {
                    const int a = __shfl_sync(0xffffffffu, naid, wp * 8 + rr);
                    const float* r = x + (size_t)a * XROW + 1;
                    if (lane < 31) {
                        const int l2 = 2 * lane;
                        pf[rr][0] = r[l2];      pf[rr][1] = r[l2 + 1];
                        pf[rr][2] = r[l2 + 62]; pf[rr][3] = r[l2 + 63];
                    }
                }
            }
        }

        // ---- layer 1: 16 rows x 32 cols (own n-half), 3-pass split-bf16 ----
        float acc[16];
        #pragma unroll
        for (int i = 0; i < 16; i++) acc[i] = 0.f;
        {
            const u64* Ar0 = Aw + rr4 * AP;
            const u64* Ar1 = Aw + (rr4 + 8) * AP;
            #pragma unroll
            for (int ks = 0; ks < 8; ks++) {
                const int q = ks * 8 + ka;
                u64 w00 = Ar0[q], w01 = Ar0[q + 4];
                u64 w10 = Ar1[q], w11 = Ar1[q + 4];
                u32 ah0 = lo32(w00), ah1 = lo32(w10), ah2 = lo32(w01), ah3 = lo32(w11);
                u32 al0 = hi32(w00), al1 = hi32(w10), al2 = hi32(w01), al3 = hi32(w11);
                #pragma unroll
                for (int nt = 0; nt < 4; nt++) {
                    const int bi = (wp * 32 + nt * 8 + rr4) * BPITCH + q;
                    u64 bp0 = Bp[bi], bp1 = Bp[bi + 4];
                    float* d = acc + nt * 4;
                    mma16(d, ah0, ah1, ah2, ah3, lo32(bp0), lo32(bp1));
                    mma16(d, ah0, ah1, ah2, ah3, hi32(bp0), hi32(bp1));
                    mma16(d, al0, al1, al2, al3, lo32(bp0), lo32(bp1));
                }
            }
        }
        BARP(bid5);   // both warps done reading features

        // ---- bias + relu -> split h1 into own cols (kpairs wp*16..wp*16+15) --
        #pragma unroll
        for (int nt = 0; nt < 4; nt++) {
            const int c = wp * 32 + nt * 8 + ka * 2;
            const int qh = wp * 16 + nt * 4 + ka;
            const float bb0 = b1s[c], bb1 = b1s[c + 1];
            float v0 = fmaxf(acc[nt * 4 + 0] + bb0, 0.f);
            float v1 = fmaxf(acc[nt * 4 + 1] + bb1, 0.f);
            Aw[rr4 * AP + qh] = split_pack(v0, v1);
            float v2 = fmaxf(acc[nt * 4 + 2] + bb0, 0.f);
            float v3 = fmaxf(acc[nt * 4 + 3] + bb1, 0.f);
            Aw[(rr4 + 8) * AP + qh] = split_pack(v2, v3);
        }
        BARP(bid5);   // h1 complete

        // ---- layer 2 (MMA, own j-half) + layer 3 partials ----
        {
            float a2c[4] = {0.f, 0.f, 0.f, 0.f};
            const u64* Ar0 = Aw + rr4 * AP;
            const u64* Ar1 = Aw + (rr4 + 8) * AP;
            #pragma unroll
            for (int ks = 0; ks < 4; ks++) {
                const int q = ks * 8 + ka;
                u64 w00 = Ar0[q], w01 = Ar0[q + 4];
                u64 w10 = Ar1[q], w11 = Ar1[q + 4];
                const int bi = (wp * 8 + rr4) * W2PITCH + q;
                u64 bp0 = W2p[bi], bp1 = W2p[bi + 4];
                mma16(a2c, lo32(w00), lo32(w10), lo32(w01), lo32(w11),
                      lo32(bp0), lo32(bp1));
                mma16(a2c, lo32(w00), lo32(w10), lo32(w01), lo32(w11),
                      hi32(bp0), hi32(bp1));
                mma16(a2c, hi32(w00), hi32(w10), hi32(w01), hi32(w11),
                      lo32(bp0), lo32(bp1));
            }
            const int j0 = wp * 8 + ka * 2;
            const float w30 = w3s[j0], w31 = w3s[j0 + 1];
            const float bb0 = b2s[j0], bb1 = b2s[j0 + 1];
            float pr  = fmaxf(a2c[0] + bb0, 0.f) * w30 + fmaxf(a2c[1] + bb1, 0.f) * w31;
            float pr8 = fmaxf(a2c[2] + bb0, 0.f) * w30 + fmaxf(a2c[3] + bb1, 0.f) * w31;
            pr  += __shfl_xor_sync(0xffffffffu, pr, 1);
            pr  += __shfl_xor_sync(0xffffffffu, pr, 2);
            pr8 += __shfl_xor_sync(0xffffffffu, pr8, 1);
            pr8 += __shfl_xor_sync(0xffffffffu, pr8, 2);
            if (ka == 0) {
                s_pt[(pair * 16 + rr4) * 2 + wp]     = pr;
                s_pt[(pair * 16 + rr4 + 8) * 2 + wp] = pr8;
            }
        }
        BARP(bid5);   // partials ready; also fences layer-2 slab reads

        // ---- combine + atomic accumulate (mask==1 for all listed atoms) ----
        if (wp == 0 && lane < 16) {
            if (slot0 + lane < cnt) {
                const int row = pair * 16 + lane;
                float v = s_pt[row * 2] + s_pt[row * 2 + 1];
                atomicAdd(&out[aid >> 6], v + cst);
            }
        }
        aid = naid;
    }
}

// ---------------- launch -----------------------------------------------------
extern "C" void kernel_launch(void* const* d_in, const int* in_sizes, int n_in,
                              void* d_out, int out_size) {
    const float* x    = (const float*)d_in[0];
    const float* mask = (const float*)d_in[1];
    const float* W1   = (const float*)d_in[2];
    const float* b1   = (const float*)d_in[3];
    const float* W2   = (const float*)d_in[4];
    const float* b2   = (const float*)d_in[5];
    const float* W3   = (const float*)d_in[6];
    const float* b3   = (const float*)d_in[7];
    float* out = (float*)d_out;

    static void* cnt_addr = nullptr;
    static int   init_done = 0;
    if (!init_done) {
        cudaGetSymbolAddress(&cnt_addr, d_cnt);
        cudaFuncSetAttribute(mol_kernel, cudaFuncAttributeMaxDynamicSharedMemorySize,
                             SMEM_TOTAL);
        init_done = 1;
    }

    cudaMemsetAsync(cnt_addr, 0, NTYPE * sizeof(int));
    setup_kernel<<<CLS_BLOCKS + NTYPE, 256>>>(x, mask, W1, b1, W2, b2, W3, b3, out);

    dim3 grid(NSLOT, NTYPE);
    mol_kernel<<<grid, NTHREADS, SMEM_TOTAL>>>(x, b1, b2, W3, b3, out);
}

// round 16
// speedup vs baseline: 1.0971x; 1.0971x over previous
#include <cuda_runtime.h>
#include <cuda_bf16.h>

typedef unsigned int       u32;
typedef unsigned long long u64;

#define BATCH    4096
#define ATOMS    64
#define NATOMS   (BATCH * ATOMS)
#define FDIM     124
#define XROW     125
#define NTYPE    8
#define H1       64
#define H2       16
#define NA       64                  // atoms per chunk (16 per warp-pair)
#define NTHREADS 256
#define LISTCAP  40960
#define NSLOT    55                  // 55*8 = 440 CTAs ~= 148 SMs x 3

#define AP       76                  // u64 per A row (62 data + 2 pad + 12 slack for z)
#define BPITCH   68                  // u64 per B row

// ---------------- SMEM layout (byte offsets) ---------------------------------
#define OFF_BP    0                          // Bp  u64[64][68] = 34816
#define OFF_A     34816                      // A   u64[64][76] = 38912
#define OFF_B1    73728                      // 256
#define OFF_B2    73984                      // 64
#define OFF_W3    74048                      // 64
#define OFF_MISC  74112                      // 16
#define SMEM_TOTAL 74128                     // 72.4KB -> 3 CTAs/SM

// ---------------- device globals ---------------------------------------------
__device__ float d_c[NTYPE];               // c_t = MLP_t(0)
__device__ int   d_cnt[NTYPE];
__device__ int   d_list[NTYPE][LISTCAP];
__device__ u64   d_w1p[NTYPE][H1 * 64];    // [t][n][kpair] (lo<<32)|hi
__device__ u64   d_w2p[NTYPE][H2 * 32];    // [t][j][hpair]

// ---------------- helpers ----------------------------------------------------
__device__ __forceinline__ u32 cvt2bf(float hi_elem, float lo_elem) {
    u32 r;
    asm("cvt.rn.bf16x2.f32 %0, %1, %2;" : "=r"(r) : "f"(hi_elem), "f"(lo_elem));
    return r;
}
__device__ __forceinline__ u64 split_pack(float fx, float fy) {
    u32 hi = cvt2bf(fy, fx);
    float ha = __uint_as_float(hi << 16);
    float hb = __uint_as_float(hi & 0xFFFF0000u);
    u32 lo = cvt2bf(fy - hb, fx - ha);
    return ((u64)lo << 32) | hi;
}
__device__ __forceinline__ void mma16(float* d, u32 a0, u32 a1, u32 a2, u32 a3,
                                      u32 b0, u32 b1) {
    asm volatile(
        "mma.sync.aligned.m16n8k16.row.col.f32.bf16.bf16.f32 "
        "{%0,%1,%2,%3}, {%4,%5,%6,%7}, {%8,%9}, {%0,%1,%2,%3};"
        : "+f"(d[0]), "+f"(d[1]), "+f"(d[2]), "+f"(d[3])
        : "r"(a0), "r"(a1), "r"(a2), "r"(a3), "r"(b0), "r"(b1));
}
__device__ __forceinline__ u32 lo32(u64 v) { return (u32)v; }
__device__ __forceinline__ u32 hi32(u64 v) { return (u32)(v >> 32); }
#define BARP(id) asm volatile("bar.sync %0, 64;" :: "r"(id) : "memory")
#define PF_L2(p) asm volatile("prefetch.global.L2 [%0];" :: "l"(p))

// ---------------- kernel 0: fused setup (classify + weight prep) -------------
#define CLS_ATOMS 1024
#define CLS_BLOCKS (NATOMS / CLS_ATOMS)     // 256
__global__ __launch_bounds__(256)
void setup_kernel(const float* __restrict__ x,
                  const float* __restrict__ mask,
                  const float* __restrict__ W1,
                  const float* __restrict__ b1,
                  const float* __restrict__ W2,
                  const float* __restrict__ b2,
                  const float* __restrict__ W3,
                  const float* __restrict__ b3,
                  float* __restrict__ out) {
    const int tid = threadIdx.x;
    if (blockIdx.x < CLS_BLOCKS) {
        __shared__ int s_cnt[NTYPE];
        __shared__ int s_base[NTYPE];
        if (tid < NTYPE) s_cnt[tid] = 0;
        __syncthreads();
        const int a0 = blockIdx.x * CLS_ATOMS + tid * 4;
        int ty[4], rk[4];
        float mv[4];
        #pragma unroll
        for (int i = 0; i < 4; i++) {
            mv[i] = mask[a0 + i];
            ty[i] = (int)x[(size_t)(a0 + i) * XROW];
        }
        #pragma unroll
        for (int i = 0; i < 4; i++)
            rk[i] = (mv[i] != 0.f) ? atomicAdd(&s_cnt[ty[i]], 1) : -1;
        __syncthreads();
        if (tid < NTYPE) s_base[tid] = atomicAdd(&d_cnt[tid], s_cnt[tid]);
        __syncthreads();
        #pragma unroll
        for (int i = 0; i < 4; i++)
            if (rk[i] >= 0)
                d_list[ty[i]][s_base[ty[i]] + rk[i]] = a0 + i;
    } else {
        const int t = blockIdx.x - CLS_BLOCKS;
        for (int i = tid; i < H1 * 64; i += 256) {
            int n = i >> 6, p = i & 63;
            u64 w = 0;
            if (p < FDIM / 2) {
                float va = W1[(size_t)t * FDIM * H1 + (2 * p) * H1 + n];
                float vb = W1[(size_t)t * FDIM * H1 + (2 * p + 1) * H1 + n];
                w = split_pack(va, vb);
            }
            d_w1p[t][i] = w;
        }
        for (int i = tid; i < H2 * 32; i += 256) {
            int j = i >> 5, p = i & 31;
            float va = W2[(size_t)t * H1 * H2 + (2 * p) * H2 + j];
            float vb = W2[(size_t)t * H1 * H2 + (2 * p + 1) * H2 + j];
            d_w2p[t][i] = split_pack(va, vb);
        }
        for (int i = tid; i < BATCH / NTYPE; i += 256)
            out[t * (BATCH / NTYPE) + i] = 0.f;
        if (tid < 16) {
            const int g = tid;
            float v = b2[t * H2 + g];
            for (int h = 0; h < H1; h++)
                v += fmaxf(b1[t * H1 + h], 0.f) * W2[t * H1 * H2 + h * H2 + g];
            float o = fmaxf(v, 0.f) * W3[t * H2 + g];
            #pragma unroll
            for (int off = 8; off > 0; off >>= 1)
                o += __shfl_xor_sync(0xffffu, o, off);
            if (g == 0) d_c[t] = o + b3[t];
        }
    }
}

// ---------------- kernel 1: warp-pair MLP, register-resident layer 2 ---------
__global__ __launch_bounds__(NTHREADS, 3)
void mol_kernel(const float* __restrict__ x,
                const float* __restrict__ b1,
                const float* __restrict__ b2,
                const float* __restrict__ W3,
                const float* __restrict__ b3,
                float* __restrict__ out) {
    extern __shared__ char smraw[];
    const int tid = threadIdx.x, wid = tid >> 5, lane = tid & 31;
    const int t = blockIdx.y;
    const int cnt = d_cnt[t];

    u64*   Bp   = (u64*)(smraw + OFF_BP);
    u64*   Ap   = (u64*)(smraw + OFF_A);
    float* b1s  = (float*)(smraw + OFF_B1);
    float* b2s  = (float*)(smraw + OFF_B2);
    float* w3s  = (float*)(smraw + OFF_W3);
    float* s_ms = (float*)(smraw + OFF_MISC);

    // ---- stage read-only shared data ONCE ----
    {
        const u64* w1 = d_w1p[t];
        for (int i = tid; i < H1 * 64; i += NTHREADS) {
            int n = i >> 6, p = i & 63;
            Bp[n * BPITCH + p] = w1[i];
        }
        if (tid < H1) b1s[tid] = b1[t * H1 + tid];
        if (tid < H2) { b2s[tid] = b2[t * H2 + tid]; w3s[tid] = W3[t * H2 + tid]; }
        if (tid == 0) {
            float tot = 0.f;
            #pragma unroll
            for (int u = 0; u < NTYPE; u++) tot += d_c[u];
            s_ms[0] = b3[t] + (tot - d_c[t]);   // b3 + correction
        }
        if (tid < 128) {                        // zero k-pads once (never rewritten)
            int r = tid >> 1, kp = 62 + (tid & 1);
            Ap[r * AP + kp] = 0ull;
        }
    }

    const int pair = wid >> 1;               // 0..3
    const int wp   = wid & 1;                // warp-in-pair
    const int bid5 = pair + 1;               // named barrier id 1..4
    const int rr4  = lane >> 2;              // fragment rows rr4, rr4+8
    const int ka   = lane & 3;
    u64* Aw = Ap + pair * 16 * AP;           // pair's 16-row slab

    // ---- W2 fragments: loop-invariant, register-resident ----
    u64 w2f[2][2][2];
    #pragma unroll
    for (int ks = 0; ks < 2; ks++)
        #pragma unroll
        for (int nt2 = 0; nt2 < 2; nt2++) {
            int bi = (nt2 * 8 + rr4) * 32 + (2 * wp + ks) * 8 + ka;
            w2f[ks][nt2][0] = d_w2p[t][bi];
            w2f[ks][nt2][1] = d_w2p[t][bi + 4];
        }

    __syncthreads();   // the ONLY block barrier
    const float cst = s_ms[0];
    const int step = NSLOT * NA;

    // ---- persistent warp-pair chunk loop ----
    for (int base = blockIdx.x * NA; base < cnt; base += step) {
        const int slot0 = base + pair * 16;

        // atom ids for the pair's 16 atoms (lanes 0..15, both warps)
        int aid = 0;
        if (lane < 16)
            aid = d_list[t][min(slot0 + lane, cnt - 1)];

        // ---- gather + split own 8 rows (pair-stride) ----
        #pragma unroll
        for (int rr = 0; rr < 8; rr += 2) {
            const int srow = wp * 8 + rr;
            const int a0id = __shfl_sync(0xffffffffu, aid, srow);
            const int a1id = __shfl_sync(0xffffffffu, aid, srow + 1);
            const float* r0 = x + (size_t)a0id * XROW + 1;
            const float* r1 = x + (size_t)a1id * XROW + 1;
            if (lane < 31) {
                const int l2 = 2 * lane;
                float f0 = r0[l2],      f1 = r0[l2 + 1];
                float f2 = r0[l2 + 62], f3 = r0[l2 + 63];
                float g0 = r1[l2],      g1 = r1[l2 + 1];
                float g2 = r1[l2 + 62], g3 = r1[l2 + 63];
                Aw[srow * AP + lane]            = split_pack(f0, f1);
                Aw[srow * AP + lane + 31]       = split_pack(f2, f3);
                Aw[(srow + 1) * AP + lane]      = split_pack(g0, g1);
                Aw[(srow + 1) * AP + lane + 31] = split_pack(g2, g3);
            }
        }

        // ---- prefetch NEXT chunk's feature rows into L2 ----
        {
            const int nbase = base + step;
            if (nbase < cnt) {
                const int r   = lane >> 2;
                const int seg = lane & 3;
                int nix = min(nbase + pair * 16 + wp * 8 + r, cnt - 1);
                int na = d_list[t][nix];
                const char* p = (const char*)(x + (size_t)na * XROW + 1) + seg * 128;
                PF_L2(p);
            }
        }
        BARP(bid5);   // pair's 16 rows complete

        // ---- layer 1: 16 rows x 32 cols (own n-half), 3-pass split-bf16 ----
        float acc[16];
        #pragma unroll
        for (int i = 0; i < 16; i++) acc[i] = 0.f;
        {
            const u64* Ar0 = Aw + rr4 * AP;
            const u64* Ar1 = Aw + (rr4 + 8) * AP;
            #pragma unroll
            for (int ks = 0; ks < 8; ks++) {
                const int q = ks * 8 + ka;
                u64 w00 = Ar0[q], w01 = Ar0[q + 4];
                u64 w10 = Ar1[q], w11 = Ar1[q + 4];
                u32 ah0 = lo32(w00), ah1 = lo32(w10), ah2 = lo32(w01), ah3 = lo32(w11);
                u32 al0 = hi32(w00), al1 = hi32(w10), al2 = hi32(w01), al3 = hi32(w11);
                #pragma unroll
                for (int nt = 0; nt < 4; nt++) {
                    const int bi = (wp * 32 + nt * 8 + rr4) * BPITCH + q;
                    u64 bp0 = Bp[bi], bp1 = Bp[bi + 4];
                    float* d = acc + nt * 4;
                    mma16(d, ah0, ah1, ah2, ah3, lo32(bp0), lo32(bp1));
                    mma16(d, ah0, ah1, ah2, ah3, hi32(bp0), hi32(bp1));
                    mma16(d, al0, al1, al2, al3, lo32(bp0), lo32(bp1));
                }
            }
        }
        BARP(bid5);   // both warps done reading features (A slab reusable)

        // ---- bias + relu -> layer-2 A fragments IN REGISTERS ----
        // layer-2 fragment == layer-1 accumulator layout (verified mapping)
        u32 fh[2][4], fl[2][4];
        #pragma unroll
        for (int ks = 0; ks < 2; ks++) {
            const int c0 = wp * 32 + 16 * ks + 2 * ka;   // nt = 2ks
            float2 bb0 = *(const float2*)(b1s + c0);
            float2 bb1 = *(const float2*)(b1s + c0 + 8); // nt = 2ks+1
            float v0 = fmaxf(acc[8 * ks + 0] + bb0.x, 0.f);
            float v1 = fmaxf(acc[8 * ks + 1] + bb0.y, 0.f);
            float v2 = fmaxf(acc[8 * ks + 2] + bb0.x, 0.f);
            float v3 = fmaxf(acc[8 * ks + 3] + bb0.y, 0.f);
            float v4 = fmaxf(acc[8 * ks + 4] + bb1.x, 0.f);
            float v5 = fmaxf(acc[8 * ks + 5] + bb1.y, 0.f);
            float v6 = fmaxf(acc[8 * ks + 6] + bb1.x, 0.f);
            float v7 = fmaxf(acc[8 * ks + 7] + bb1.y, 0.f);
            u64 p;
            p = split_pack(v0, v1); fh[ks][0] = lo32(p); fl[ks][0] = hi32(p);
            p = split_pack(v2, v3); fh[ks][1] = lo32(p); fl[ks][1] = hi32(p);
            p = split_pack(v4, v5); fh[ks][2] = lo32(p); fl[ks][2] = hi32(p);
            p = split_pack(v6, v7); fh[ks][3] = lo32(p); fl[ks][3] = hi32(p);
        }

        // ---- layer 2 MMA: own k-half, ALL 16 j, 3-pass ----
        float a2c[8];
        #pragma unroll
        for (int i = 0; i < 8; i++) a2c[i] = 0.f;
        #pragma unroll
        for (int ks = 0; ks < 2; ks++)
            #pragma unroll
            for (int nt2 = 0; nt2 < 2; nt2++) {
                u32 bh0 = lo32(w2f[ks][nt2][0]), bh1 = lo32(w2f[ks][nt2][1]);
                u32 bl0 = hi32(w2f[ks][nt2][0]), bl1 = hi32(w2f[ks][nt2][1]);
                float* d = a2c + nt2 * 4;
                mma16(d, fh[ks][0], fh[ks][1], fh[ks][2], fh[ks][3], bh0, bh1);
                mma16(d, fh[ks][0], fh[ks][1], fh[ks][2], fh[ks][3], bl0, bl1);
                mma16(d, fl[ks][0], fl[ks][1], fl[ks][2], fl[ks][3], bh0, bh1);
            }

        // ---- pre-relu z-partial exchange via A-slab slack (kpairs 64..75) ----
        if (wp == 0) {
            #pragma unroll
            for (int nt2 = 0; nt2 < 2; nt2++) {
                const int j0 = nt2 * 8 + 2 * ka;
                float* z0 = (float*)(Aw + rr4 * AP + 64) + j0;
                float* z8 = (float*)(Aw + (rr4 + 8) * AP + 64) + j0;
                *(float2*)z0 = make_float2(a2c[nt2 * 4 + 0], a2c[nt2 * 4 + 1]);
                *(float2*)z8 = make_float2(a2c[nt2 * 4 + 2], a2c[nt2 * 4 + 3]);
            }
        }
        BARP(bid5);   // z partials ready

        // ---- wp1: combine, relu, layer 3, reduce, accumulate ----
        if (wp == 1) {
            float pr = 0.f, pr8 = 0.f;
            #pragma unroll
            for (int nt2 = 0; nt2 < 2; nt2++) {
                const int j0 = nt2 * 8 + 2 * ka;
                float2 z0 = *(const float2*)((float*)(Aw + rr4 * AP + 64) + j0);
                float2 z8 = *(const float2*)((float*)(Aw + (rr4 + 8) * AP + 64) + j0);
                const float w30 = w3s[j0], w31 = w3s[j0 + 1];
                const float bb0 = b2s[j0], bb1 = b2s[j0 + 1];
                pr  += fmaxf(a2c[nt2 * 4 + 0] + z0.x + bb0, 0.f) * w30
                     + fmaxf(a2c[nt2 * 4 + 1] + z0.y + bb1, 0.f) * w31;
                pr8 += fmaxf(a2c[nt2 * 4 + 2] + z8.x + bb0, 0.f) * w30
                     + fmaxf(a2c[nt2 * 4 + 3] + z8.y + bb1, 0.f) * w31;
            }
            pr  += __shfl_xor_sync(0xffffffffu, pr, 1);
            pr  += __shfl_xor_sync(0xffffffffu, pr, 2);
            pr8 += __shfl_xor_sync(0xffffffffu, pr8, 1);
            pr8 += __shfl_xor_sync(0xffffffffu, pr8, 2);
            const int a0id = __shfl_sync(0xffffffffu, aid, rr4);
            const int a8id = __shfl_sync(0xffffffffu, aid, rr4 + 8);
            if (ka == 0) {
                if (slot0 + rr4 < cnt)
                    atomicAdd(&out[a0id >> 6], pr + cst);
                if (slot0 + 8 + rr4 < cnt)
                    atomicAdd(&out[a8id >> 6], pr8 + cst);
            }
        }
        // next iteration's BARP(1) orders slab reuse against wp1's z reads
    }
}

// ---------------- launch -----------------------------------------------------
extern "C" void kernel_launch(void* const* d_in, const int* in_sizes, int n_in,
                              void* d_out, int out_size) {
    const float* x    = (const float*)d_in[0];
    const float* mask = (const float*)d_in[1];
    const float* W1   = (const float*)d_in[2];
    const float* b1   = (const float*)d_in[3];
    const float* W2   = (const float*)d_in[4];
    const float* b2   = (const float*)d_in[5];
    const float* W3   = (const float*)d_in[6];
    const float* b3   = (const float*)d_in[7];
    float* out = (float*)d_out;

    static void* cnt_addr = nullptr;
    static int   init_done = 0;
    if (!init_done) {
        cudaGetSymbolAddress(&cnt_addr, d_cnt);
        cudaFuncSetAttribute(mol_kernel, cudaFuncAttributeMaxDynamicSharedMemorySize,
                             SMEM_TOTAL);
        init_done = 1;
    }

    cudaMemsetAsync(cnt_addr, 0, NTYPE * sizeof(int));
    setup_kernel<<<CLS_BLOCKS + NTYPE, 256>>>(x, mask, W1, b1, W2, b2, W3, b3, out);

    dim3 grid(NSLOT, NTYPE);
    mol_kernel<<<grid, NTHREADS, SMEM_TOTAL>>>(x, b1, b2, W3, b3, out);
}